// round 13
// baseline (speedup 1.0000x reference)
#include <cuda_runtime.h>
#include <cstdint>

#define N_NODES 100000
#define DFEAT   64
#define NCOEF   8
#define KTOT    576
#define NGRAPHS 512
#define NTARG   10
#define NEDGES  1200000

#define NTILE     128        // nodes per block in k_kan64
#define TPB       256
#define SF_STRIDE 132        // 528B rows: 16B aligned; row-to-row 16 banks mod 128B
#define SW_STRIDE 132
#define KAN_SMEM  ((64 * SW_STRIDE + NTILE * SF_STRIDE) * 4)   // 101376 B

// ---------------- static device scratch (no allocation allowed) -------------
__device__ __align__(128) float g_y [N_NODES * DFEAT];
__device__ __align__(128) float g_h [N_NODES * DFEAT];
__device__ __align__(128) float g_y2[N_NODES * DFEAT];
__device__ __align__(128) float g_pool[NGRAPHS * DFEAT];
__device__ __align__(128) float g_W0[DFEAT * KTOT];
__device__ __align__(128) float g_W1[DFEAT * KTOT];
__device__ __align__(128) float g_Wh[NTARG * KTOT];

__device__ __forceinline__ float silu_f(float v) {
    return v / (1.0f + __expf(-v));
}

// closed-form uniform cubic B-spline: write the 8 basis values to dst[0..7].
// grid: t_j = (j-3)*0.4 - 1, j=0..11; support [-2.2, 2.2)
__device__ __forceinline__ void bspl8_store(float x, float* dst) {
    *(float4*)dst       = make_float4(0.f, 0.f, 0.f, 0.f);
    *(float4*)(dst + 4) = make_float4(0.f, 0.f, 0.f, 0.f);
    float p = (x + 2.2f) * 2.5f;
    if (p >= 0.0f && p < 11.0f) {
        int c = (int)p;            // cell index 0..10
        float u  = p - (float)c;
        float um = 1.0f - u;
        float u2 = u * u;
        float u3 = u2 * u;
        float w_s0 = u3 * (1.0f / 6.0f);                                        // B_c
        float w_s1 = (1.0f + 3.0f * u + 3.0f * u2 - 3.0f * u3) * (1.0f / 6.0f); // B_{c-1}
        float w_s2 = (4.0f - 6.0f * u2 + 3.0f * u3) * (1.0f / 6.0f);            // B_{c-2}
        float w_s3 = um * um * um * (1.0f / 6.0f);                              // B_{c-3}
        if (c     <= 7)               dst[c]     = w_s0;
        if (c - 1 >= 0 && c - 1 <= 7) dst[c - 1] = w_s1;
        if (c - 2 >= 0 && c - 2 <= 7) dst[c - 2] = w_s2;
        if (c - 3 >= 0)               dst[c - 3] = w_s3;
    }
}

__device__ __forceinline__ void bspl8_reg(float x, float b[8]) {
    float tmp[8];
    bspl8_store(x, tmp);
#pragma unroll
    for (int g = 0; g < 8; g++) b[g] = tmp[g];
}

// ---------------- merged init: W_eff prep + pool zero + y0 copy -------------
#define PREP_BLOCKS ((DFEAT * KTOT + TPB - 1) / TPB)          // 144
#define COPY_N4     (N_NODES * DFEAT / 4)                     // 1.6M
#define COPY_BLOCKS ((COPY_N4 + TPB - 1) / TPB)               // 6250
__global__ void k_init(const float* __restrict__ bw0, const float* __restrict__ sw0, const float* __restrict__ sc0,
                       const float* __restrict__ bw1, const float* __restrict__ sw1, const float* __restrict__ sc1,
                       const float* __restrict__ bwh, const float* __restrict__ swh, const float* __restrict__ sch,
                       const float4* __restrict__ x4) {
    if (blockIdx.x >= PREP_BLOCKS) {
        int i = (blockIdx.x - PREP_BLOCKS) * blockDim.x + threadIdx.x;
        if (i < COPY_N4) ((float4*)g_y)[i] = x4[i];
        return;
    }
    int idx = blockIdx.x * blockDim.x + threadIdx.x;
    if (idx >= DFEAT * KTOT) return;
    if (idx < NGRAPHS * DFEAT) g_pool[idx] = 0.0f;   // fused pool zeroing
    int o = idx / KTOT, k = idx % KTOT;
    float v0, v1;
    if (k < DFEAT) {
        v0 = bw0[o * DFEAT + k];
        v1 = bw1[o * DFEAT + k];
    } else {
        int k2 = k - DFEAT;
        int i = k2 >> 3, g = k2 & 7;
        v0 = sw0[(o * DFEAT + i) * NCOEF + g] * sc0[o * DFEAT + i];
        v1 = sw1[(o * DFEAT + i) * NCOEF + g] * sc1[o * DFEAT + i];
    }
    g_W0[idx] = v0;
    g_W1[idx] = v1;
    if (o < NTARG) {
        float vh;
        if (k < DFEAT) {
            vh = bwh[o * DFEAT + k];
        } else {
            int k2 = k - DFEAT;
            int i = k2 >> 3, g = k2 & 7;
            vh = swh[(o * DFEAT + i) * NCOEF + g] * sch[o * DFEAT + i];
        }
        g_Wh[o * KTOT + k] = vh;
    }
}

// ---------------- edge scatter: dstbuf[dst] += feat[src] --------------------
__global__ void k_scatter(const float* __restrict__ feat, float* __restrict__ dstbuf,
                          const int* __restrict__ ei) {
    int idx = blockIdx.x * blockDim.x + threadIdx.x;
    if (idx >= NEDGES * 16) return;
    int e = idx >> 4;
    int c = idx & 15;
    int s = __ldg(&ei[e]);
    int d = __ldg(&ei[NEDGES + e]);
    float4 v = *(const float4*)(feat + (size_t)s * DFEAT + c * 4);
    float* p = dstbuf + (size_t)d * DFEAT + c * 4;
    asm volatile("red.global.add.v4.f32 [%0], {%1,%2,%3,%4};"
                 :: "l"(p), "f"(v.x), "f"(v.y), "f"(v.z), "f"(v.w)
                 : "memory");
}

// ---------------- GEMM helper over a KW-wide staged region ------------------
template<int KW>
__device__ __forceinline__ void gemm_stage(const float* __restrict__ sW,
                                           const float* __restrict__ sF,
                                           float acc[4][8], int ng, int og) {
#pragma unroll
    for (int k = 0; k < KW; k += 4) {
        float4 fv[4];
#pragma unroll
        for (int nn = 0; nn < 4; nn++)
            fv[nn] = *(const float4*)&sF[(nn * 32 + ng) * SF_STRIDE + k];
#pragma unroll
        for (int oo = 0; oo < 8; oo++) {
            float4 wv = *(const float4*)&sW[(oo * 8 + og) * SW_STRIDE + k];
#pragma unroll
            for (int nn = 0; nn < 4; nn++) {
                acc[nn][oo] += fv[nn].x * wv.x + fv[nn].y * wv.y
                             + fv[nn].z * wv.z + fv[nn].w * wv.w;
            }
        }
    }
}

// ---------------- fused KAN 64->64 layer (4x8 tile, 128-wide K stages) ------
// 128-node tile, 256 threads, thread tile 4 nodes x 8 outs (interleaved node
// map: thread (ng, og) covers nodes {ng, ng+32, ng+64, ng+96}).
// K processed in 5 stages: 4 x 128-wide (logical chunk pairs {0,1}..{6,7})
// + 1 x 64-wide tail (chunk 8). Logical chunk 0 = silu features; chunk c>=1 =
// spline bases for inputs (c-1)*8..(c-1)*8+7.
// sF/sW strides 132 (528B == 16 mod 128): fv rows 16 banks apart, wv permuted
// rows ((o&7)<<3|o>>3) cover offsets {0,16,...,112} mod 128 -> conflict-free.
// Epilogue: batch==nullptr -> store hout (+ optional dual store hout2);
//           batch!=nullptr -> red into g_pool[batch[n]] (fused add-pool).
__global__ __launch_bounds__(TPB, 2) void k_kan64(const float* __restrict__ yin,
                                                  float* __restrict__ hout,
                                                  float* __restrict__ hout2,
                                                  const float* __restrict__ W,
                                                  const int* __restrict__ batch) {
    extern __shared__ float smem[];
    float* sW = smem;                    // 64 * 132
    float* sF = smem + 64 * SW_STRIDE;   // 128 * 132

    int tid = threadIdx.x;
    int nb = blockIdx.x * NTILE;

    float acc[4][8];
#pragma unroll
    for (int a = 0; a < 4; a++)
#pragma unroll
        for (int b = 0; b < 8; b++) acc[a][b] = 0.0f;

    int ng = tid >> 3;  // 0..31
    int og = tid & 7;   // 0..7 -> outs og*8 .. og*8+7

    // ---- stages 0..3: 128-wide (chunk pair 2s, 2s+1) ----
    for (int s = 0; s < 4; s++) {
        __syncthreads();
        // stage W: 2048 float4 (rows o, cols = 128 floats from k=s*128)
#pragma unroll
        for (int r = 0; r < 8; r++) {
            int idx = r * TPB + tid;          // 0..2047
            int o = idx >> 5, kq = idx & 31;
            float4 wv4 = *(const float4*)&W[o * KTOT + s * 128 + kq * 4];
            int pr = ((o & 7) << 3) | (o >> 3);
            *(float4*)&sW[pr * SW_STRIDE + kq * 4] = wv4;
        }
        // stage F
        if (s == 0) {
            // cols 0..63: silu(y)
#pragma unroll
            for (int r = 0; r < 8; r++) {
                int idx = r * TPB + tid;      // 0..2047 float4 units
                int n = idx >> 4, kq = idx & 15;
                int gn = nb + n; if (gn >= N_NODES) gn = N_NODES - 1;
                float4 v = *(const float4*)&yin[(size_t)gn * DFEAT + kq * 4];
                float4 sv;
                sv.x = silu_f(v.x); sv.y = silu_f(v.y);
                sv.z = silu_f(v.z); sv.w = silu_f(v.w);
                *(float4*)&sF[n * SF_STRIDE + kq * 4] = sv;
            }
            // cols 64..127: basis of inputs 0..7
#pragma unroll
            for (int r = 0; r < 4; r++) {
                int idx = r * TPB + tid;      // 0..1023 (n, ii)
                int n = idx >> 3, ii = idx & 7;
                int gn = nb + n; if (gn >= N_NODES) gn = N_NODES - 1;
                float v = yin[(size_t)gn * DFEAT + ii];
                bspl8_store(v, &sF[n * SF_STRIDE + 64 + ii * 8]);
            }
        } else {
            // cols 0..127: basis of inputs (2s-1)*8 .. (2s+1)*8-1  (16 inputs)
#pragma unroll
            for (int r = 0; r < 8; r++) {
                int idx = r * TPB + tid;      // 0..2047 (n, ii2)
                int n = idx >> 4, ii2 = idx & 15;
                int gn = nb + n; if (gn >= N_NODES) gn = N_NODES - 1;
                float v = yin[(size_t)gn * DFEAT + (2 * s - 1) * 8 + ii2];
                bspl8_store(v, &sF[n * SF_STRIDE + ii2 * 8]);
            }
        }
        __syncthreads();
        gemm_stage<128>(sW, sF, acc, ng, og);
    }

    // ---- stage 4: 64-wide tail (chunk 8 = inputs 56..63) ----
    {
        __syncthreads();
#pragma unroll
        for (int r = 0; r < 4; r++) {
            int idx = r * TPB + tid;          // 0..1023
            int o = idx >> 4, kq = idx & 15;
            float4 wv4 = *(const float4*)&W[o * KTOT + 512 + kq * 4];
            int pr = ((o & 7) << 3) | (o >> 3);
            *(float4*)&sW[pr * SW_STRIDE + kq * 4] = wv4;
        }
#pragma unroll
        for (int r = 0; r < 4; r++) {
            int idx = r * TPB + tid;          // 0..1023 (n, ii)
            int n = idx >> 3, ii = idx & 7;
            int gn = nb + n; if (gn >= N_NODES) gn = N_NODES - 1;
            float v = yin[(size_t)gn * DFEAT + 56 + ii];
            bspl8_store(v, &sF[n * SF_STRIDE + ii * 8]);
        }
        __syncthreads();
        gemm_stage<64>(sW, sF, acc, ng, og);
    }

    // epilogue: thread covers nodes nn*32+ng, outputs og*8..og*8+7
#pragma unroll
    for (int nn = 0; nn < 4; nn++) {
        int gn = nb + nn * 32 + ng;
        if (gn < N_NODES) {
            float4 v0 = make_float4(acc[nn][0], acc[nn][1], acc[nn][2], acc[nn][3]);
            float4 v1 = make_float4(acc[nn][4], acc[nn][5], acc[nn][6], acc[nn][7]);
            if (batch) {
                int g = __ldg(&batch[gn]);
                float* p = g_pool + g * DFEAT + og * 8;
                asm volatile("red.global.add.v4.f32 [%0], {%1,%2,%3,%4};"
                             :: "l"(p), "f"(v0.x), "f"(v0.y), "f"(v0.z), "f"(v0.w) : "memory");
                asm volatile("red.global.add.v4.f32 [%0], {%1,%2,%3,%4};"
                             :: "l"(p + 4), "f"(v1.x), "f"(v1.y), "f"(v1.z), "f"(v1.w) : "memory");
            } else {
                size_t base = (size_t)gn * DFEAT + og * 8;
                *(float4*)(hout + base)     = v0;
                *(float4*)(hout + base + 4) = v1;
                if (hout2) {
                    *(float4*)(hout2 + base)     = v0;
                    *(float4*)(hout2 + base + 4) = v1;
                }
            }
        }
    }
}

// ---------------- KAN head 64 -> 10 over pooled graphs ----------------------
__global__ void k_head(float* __restrict__ out) {
    __shared__ float sF[KTOT];
    int g = blockIdx.x;
    int t = threadIdx.x;  // 64 threads
    float v = g_pool[g * DFEAT + t];
    sF[t] = silu_f(v);
    float b[8];
    bspl8_reg(v, b);
#pragma unroll
    for (int gg = 0; gg < 8; gg++) sF[DFEAT + t * 8 + gg] = b[gg];
    __syncthreads();
    if (t < NTARG) {
        const float* w = g_Wh + t * KTOT;
        float acc = 0.0f;
#pragma unroll 8
        for (int k = 0; k < KTOT; k++) acc += sF[k] * w[k];
        out[g * NTARG + t] = acc;
    }
}

// ---------------- launch -----------------------------------------------------
extern "C" void kernel_launch(void* const* d_in, const int* in_sizes, int n_in,
                              void* d_out, int out_size) {
    const float* x      = (const float*)d_in[0];
    const int*   ei     = (const int*)d_in[1];
    const int*   batch  = (const int*)d_in[2];
    const float* bw0    = (const float*)d_in[3];
    const float* sw0    = (const float*)d_in[4];
    const float* sc0    = (const float*)d_in[5];
    const float* bw1    = (const float*)d_in[6];
    const float* sw1    = (const float*)d_in[7];
    const float* sc1    = (const float*)d_in[8];
    const float* bwh    = (const float*)d_in[9];
    const float* swh    = (const float*)d_in[10];
    const float* sch    = (const float*)d_in[11];
    float* out = (float*)d_out;

    float *p_y, *p_h, *p_y2, *p_W0, *p_W1;
    cudaGetSymbolAddress((void**)&p_y,  g_y);
    cudaGetSymbolAddress((void**)&p_h,  g_h);
    cudaGetSymbolAddress((void**)&p_y2, g_y2);
    cudaGetSymbolAddress((void**)&p_W0, g_W0);
    cudaGetSymbolAddress((void**)&p_W1, g_W1);

    cudaFuncSetAttribute(k_kan64, cudaFuncAttributeMaxDynamicSharedMemorySize, KAN_SMEM);

    const int scat_blocks = (NEDGES * 16 + 255) / 256;
    const int kan_blocks = (N_NODES + NTILE - 1) / NTILE;

    // merged: effective weights + pool zeroing + y0 = x copy
    k_init<<<PREP_BLOCKS + COPY_BLOCKS, TPB>>>(bw0, sw0, sc0, bw1, sw1, sc1,
                                               bwh, swh, sch, (const float4*)x);

    // layer 0: y0 = x + agg(x); h0 = KAN(y0), dual-stored into g_h and g_y2
    k_scatter<<<scat_blocks, 256>>>(x, p_y, ei);
    k_kan64<<<kan_blocks, TPB, KAN_SMEM>>>(p_y, p_h, p_y2, p_W0, (const int*)nullptr);

    // layer 1: y1 = h0 + agg(h0) (y2 pre-seeded by dual store);
    // h1 = KAN(y1) pooled directly into g_pool (fused global_add_pool)
    k_scatter<<<scat_blocks, 256>>>(p_h, p_y2, ei);
    k_kan64<<<kan_blocks, TPB, KAN_SMEM>>>(p_y2, (float*)nullptr, (float*)nullptr, p_W1, batch);

    // head
    k_head<<<NGRAPHS, DFEAT>>>(out);
}

// round 14
// speedup vs baseline: 1.0743x; 1.0743x over previous
#include <cuda_runtime.h>
#include <cstdint>

#define N_NODES 100000
#define DFEAT   64
#define NCOEF   8
#define KTOT    576
#define NGRAPHS 512
#define NTARG   10
#define NEDGES  1200000

#define NTILE     128        // nodes per block in k_kan64
#define TPB       256
#define SF_STRIDE 68         // 272B rows: 16B aligned; warp-adjacent rows 16 banks apart
#define SW_STRIDE 68
#define KAN_SMEM  ((64 * SW_STRIDE + NTILE * SF_STRIDE) * 4)   // 52224 B

// ---------------- static device scratch (no allocation allowed) -------------
__device__ __align__(128) float g_y [N_NODES * DFEAT];
__device__ __align__(128) float g_h [N_NODES * DFEAT];
__device__ __align__(128) float g_y2[N_NODES * DFEAT];
__device__ __align__(128) float g_pool[NGRAPHS * DFEAT];
__device__ __align__(128) float g_W0[DFEAT * KTOT];
__device__ __align__(128) float g_W1[DFEAT * KTOT];
__device__ __align__(128) float g_Wh[NTARG * KTOT];

__device__ __forceinline__ float silu_f(float v) {
    return v / (1.0f + __expf(-v));
}

// closed-form uniform cubic B-spline: write the 8 basis values to dst[0..7].
// grid: t_j = (j-3)*0.4 - 1, j=0..11; support [-2.2, 2.2)
__device__ __forceinline__ void bspl8_store(float x, float* dst) {
    *(float4*)dst       = make_float4(0.f, 0.f, 0.f, 0.f);
    *(float4*)(dst + 4) = make_float4(0.f, 0.f, 0.f, 0.f);
    float p = (x + 2.2f) * 2.5f;
    if (p >= 0.0f && p < 11.0f) {
        int c = (int)p;            // cell index 0..10
        float u  = p - (float)c;
        float um = 1.0f - u;
        float u2 = u * u;
        float u3 = u2 * u;
        float w_s0 = u3 * (1.0f / 6.0f);                                        // B_c
        float w_s1 = (1.0f + 3.0f * u + 3.0f * u2 - 3.0f * u3) * (1.0f / 6.0f); // B_{c-1}
        float w_s2 = (4.0f - 6.0f * u2 + 3.0f * u3) * (1.0f / 6.0f);            // B_{c-2}
        float w_s3 = um * um * um * (1.0f / 6.0f);                              // B_{c-3}
        if (c     <= 7)               dst[c]     = w_s0;
        if (c - 1 >= 0 && c - 1 <= 7) dst[c - 1] = w_s1;
        if (c - 2 >= 0 && c - 2 <= 7) dst[c - 2] = w_s2;
        if (c - 3 >= 0)               dst[c - 3] = w_s3;
    }
}

__device__ __forceinline__ void bspl8_reg(float x, float b[8]) {
    float tmp[8];
    bspl8_store(x, tmp);
#pragma unroll
    for (int g = 0; g < 8; g++) b[g] = tmp[g];
}

// ---------------- merged init: W_eff prep + pool zero + y0 copy -------------
#define PREP_BLOCKS ((DFEAT * KTOT + TPB - 1) / TPB)          // 144
#define COPY_N4     (N_NODES * DFEAT / 4)                     // 1.6M
#define COPY_BLOCKS ((COPY_N4 + TPB - 1) / TPB)               // 6250
__global__ void k_init(const float* __restrict__ bw0, const float* __restrict__ sw0, const float* __restrict__ sc0,
                       const float* __restrict__ bw1, const float* __restrict__ sw1, const float* __restrict__ sc1,
                       const float* __restrict__ bwh, const float* __restrict__ swh, const float* __restrict__ sch,
                       const float4* __restrict__ x4) {
    if (blockIdx.x >= PREP_BLOCKS) {
        int i = (blockIdx.x - PREP_BLOCKS) * blockDim.x + threadIdx.x;
        if (i < COPY_N4) ((float4*)g_y)[i] = x4[i];
        return;
    }
    int idx = blockIdx.x * blockDim.x + threadIdx.x;
    if (idx >= DFEAT * KTOT) return;
    if (idx < NGRAPHS * DFEAT) g_pool[idx] = 0.0f;   // fused pool zeroing
    int o = idx / KTOT, k = idx % KTOT;
    float v0, v1;
    if (k < DFEAT) {
        v0 = bw0[o * DFEAT + k];
        v1 = bw1[o * DFEAT + k];
    } else {
        int k2 = k - DFEAT;
        int i = k2 >> 3, g = k2 & 7;
        v0 = sw0[(o * DFEAT + i) * NCOEF + g] * sc0[o * DFEAT + i];
        v1 = sw1[(o * DFEAT + i) * NCOEF + g] * sc1[o * DFEAT + i];
    }
    g_W0[idx] = v0;
    g_W1[idx] = v1;
    if (o < NTARG) {
        float vh;
        if (k < DFEAT) {
            vh = bwh[o * DFEAT + k];
        } else {
            int k2 = k - DFEAT;
            int i = k2 >> 3, g = k2 & 7;
            vh = swh[(o * DFEAT + i) * NCOEF + g] * sch[o * DFEAT + i];
        }
        g_Wh[o * KTOT + k] = vh;
    }
}

// ---------------- edge scatter: dstbuf[dst] += feat[src] --------------------
__global__ void k_scatter(const float* __restrict__ feat, float* __restrict__ dstbuf,
                          const int* __restrict__ ei) {
    int idx = blockIdx.x * blockDim.x + threadIdx.x;
    if (idx >= NEDGES * 16) return;
    int e = idx >> 4;
    int c = idx & 15;
    int s = __ldg(&ei[e]);
    int d = __ldg(&ei[NEDGES + e]);
    float4 v = *(const float4*)(feat + (size_t)s * DFEAT + c * 4);
    float* p = dstbuf + (size_t)d * DFEAT + c * 4;
    asm volatile("red.global.add.v4.f32 [%0], {%1,%2,%3,%4};"
                 :: "l"(p), "f"(v.x), "f"(v.y), "f"(v.z), "f"(v.w)
                 : "memory");
}

// ---------------- fused KAN 64->64 layer (R12 core, proven 232us) -----------
// 128-node tile, 256 threads, thread tile 4 nodes x 8 outs (interleaved node
// map: thread (ng, og) covers nodes {ng, ng+32, ng+64, ng+96}).
// K processed in 9 chunks of 64 (chunk 0 = silu, chunks 1..8 = 8 spline bases
// per input group).
// sF: stride 68 -> warp-consecutive ng rows land 16 banks apart, conflict-free.
// sW: rows permuted ((o&7)<<3 | o>>3), stride 68 -> the 8 per-oo addresses
// cover offsets {0,16,...,112} mod 128, conflict-free.
// Epilogue modes:
//   batch == nullptr: store result to hout (+ optional dual store to hout2).
//   batch != nullptr: red.global.add result into g_pool[batch[n]] (fused
//                     global_add_pool); hout/hout2 unused.
__global__ __launch_bounds__(TPB, 2) void k_kan64(const float* __restrict__ yin,
                                                  float* __restrict__ hout,
                                                  float* __restrict__ hout2,
                                                  const float* __restrict__ W,
                                                  const int* __restrict__ batch) {
    extern __shared__ float smem[];
    float* sW = smem;                    // 64 * 68
    float* sF = smem + 64 * SW_STRIDE;   // 128 * 68

    int tid = threadIdx.x;
    int nb = blockIdx.x * NTILE;

    float acc[4][8];
#pragma unroll
    for (int a = 0; a < 4; a++)
#pragma unroll
        for (int b = 0; b < 8; b++) acc[a][b] = 0.0f;

    int ng = tid >> 3;  // 0..31
    int og = tid & 7;   // 0..7 -> outs og*8 .. og*8+7

    for (int kc = 0; kc < 9; kc++) {
        __syncthreads();
        // stage W chunk: 1024 float4, row-permuted
#pragma unroll
        for (int r = 0; r < 4; r++) {
            int idx = r * TPB + tid;         // 0..1023
            int o = idx >> 4, kq = idx & 15;
            float4 wv4 = *(const float4*)&W[o * KTOT + kc * 64 + kq * 4];
            int pr = ((o & 7) << 3) | (o >> 3);
            *(float4*)&sW[pr * SW_STRIDE + kq * 4] = wv4;
        }
        // stage F chunk
        if (kc == 0) {
#pragma unroll
            for (int r = 0; r < 8; r++) {
                int idx = r * TPB + tid;     // 0..2047 float4 units
                int n = idx >> 4, kq = idx & 15;
                int gn = nb + n; if (gn >= N_NODES) gn = N_NODES - 1;
                float4 v = *(const float4*)&yin[(size_t)gn * DFEAT + kq * 4];
                float4 s;
                s.x = silu_f(v.x); s.y = silu_f(v.y);
                s.z = silu_f(v.z); s.w = silu_f(v.w);
                *(float4*)&sF[n * SF_STRIDE + kq * 4] = s;
            }
        } else {
#pragma unroll
            for (int r = 0; r < 4; r++) {
                int idx = r * TPB + tid;     // 0..1023 (n, ii)
                int n = idx >> 3, ii = idx & 7;
                int gn = nb + n; if (gn >= N_NODES) gn = N_NODES - 1;
                float v = yin[(size_t)gn * DFEAT + (kc - 1) * 8 + ii];
                bspl8_store(v, &sF[n * SF_STRIDE + ii * 8]);
            }
        }
        __syncthreads();

        // GEMM over this 64-wide K chunk
#pragma unroll
        for (int k = 0; k < 64; k += 4) {
            float4 fv[4];
#pragma unroll
            for (int nn = 0; nn < 4; nn++)
                fv[nn] = *(const float4*)&sF[(nn * 32 + ng) * SF_STRIDE + k];
#pragma unroll
            for (int oo = 0; oo < 8; oo++) {
                float4 wv = *(const float4*)&sW[(oo * 8 + og) * SW_STRIDE + k];
#pragma unroll
                for (int nn = 0; nn < 4; nn++) {
                    acc[nn][oo] += fv[nn].x * wv.x + fv[nn].y * wv.y
                                 + fv[nn].z * wv.z + fv[nn].w * wv.w;
                }
            }
        }
    }

    // epilogue: thread covers nodes nn*32+ng, outputs og*8..og*8+7
#pragma unroll
    for (int nn = 0; nn < 4; nn++) {
        int gn = nb + nn * 32 + ng;
        if (gn < N_NODES) {
            float4 v0 = make_float4(acc[nn][0], acc[nn][1], acc[nn][2], acc[nn][3]);
            float4 v1 = make_float4(acc[nn][4], acc[nn][5], acc[nn][6], acc[nn][7]);
            if (batch) {
                // fused global_add_pool: red into g_pool[batch[gn]]
                int g = __ldg(&batch[gn]);
                float* p = g_pool + g * DFEAT + og * 8;
                asm volatile("red.global.add.v4.f32 [%0], {%1,%2,%3,%4};"
                             :: "l"(p), "f"(v0.x), "f"(v0.y), "f"(v0.z), "f"(v0.w) : "memory");
                asm volatile("red.global.add.v4.f32 [%0], {%1,%2,%3,%4};"
                             :: "l"(p + 4), "f"(v1.x), "f"(v1.y), "f"(v1.z), "f"(v1.w) : "memory");
            } else {
                size_t base = (size_t)gn * DFEAT + og * 8;
                *(float4*)(hout + base)     = v0;
                *(float4*)(hout + base + 4) = v1;
                if (hout2) {
                    *(float4*)(hout2 + base)     = v0;
                    *(float4*)(hout2 + base + 4) = v1;
                }
            }
        }
    }
}

// ---------------- KAN head 64 -> 10 over pooled graphs ----------------------
__global__ void k_head(float* __restrict__ out) {
    __shared__ float sF[KTOT];
    int g = blockIdx.x;
    int t = threadIdx.x;  // 64 threads
    float v = g_pool[g * DFEAT + t];
    sF[t] = silu_f(v);
    float b[8];
    bspl8_reg(v, b);
#pragma unroll
    for (int gg = 0; gg < 8; gg++) sF[DFEAT + t * 8 + gg] = b[gg];
    __syncthreads();
    if (t < NTARG) {
        const float* w = g_Wh + t * KTOT;
        float acc = 0.0f;
#pragma unroll 8
        for (int k = 0; k < KTOT; k++) acc += sF[k] * w[k];
        out[g * NTARG + t] = acc;
    }
}

// ---------------- launch -----------------------------------------------------
extern "C" void kernel_launch(void* const* d_in, const int* in_sizes, int n_in,
                              void* d_out, int out_size) {
    const float* x      = (const float*)d_in[0];
    const int*   ei     = (const int*)d_in[1];
    const int*   batch  = (const int*)d_in[2];
    const float* bw0    = (const float*)d_in[3];
    const float* sw0    = (const float*)d_in[4];
    const float* sc0    = (const float*)d_in[5];
    const float* bw1    = (const float*)d_in[6];
    const float* sw1    = (const float*)d_in[7];
    const float* sc1    = (const float*)d_in[8];
    const float* bwh    = (const float*)d_in[9];
    const float* swh    = (const float*)d_in[10];
    const float* sch    = (const float*)d_in[11];
    float* out = (float*)d_out;

    float *p_y, *p_h, *p_y2, *p_W0, *p_W1;
    cudaGetSymbolAddress((void**)&p_y,  g_y);
    cudaGetSymbolAddress((void**)&p_h,  g_h);
    cudaGetSymbolAddress((void**)&p_y2, g_y2);
    cudaGetSymbolAddress((void**)&p_W0, g_W0);
    cudaGetSymbolAddress((void**)&p_W1, g_W1);

    cudaFuncSetAttribute(k_kan64, cudaFuncAttributeMaxDynamicSharedMemorySize, KAN_SMEM);

    const int scat_blocks = (NEDGES * 16 + 255) / 256;
    const int kan_blocks = (N_NODES + NTILE - 1) / NTILE;

    // merged: effective weights + pool zeroing + y0 = x copy
    k_init<<<PREP_BLOCKS + COPY_BLOCKS, TPB>>>(bw0, sw0, sc0, bw1, sw1, sc1,
                                               bwh, swh, sch, (const float4*)x);

    // layer 0: y0 = x + agg(x); h0 = KAN(y0), dual-stored into g_h and g_y2
    k_scatter<<<scat_blocks, 256>>>(x, p_y, ei);
    k_kan64<<<kan_blocks, TPB, KAN_SMEM>>>(p_y, p_h, p_y2, p_W0, (const int*)nullptr);

    // layer 1: y1 = h0 + agg(h0) (y2 pre-seeded by dual store);
    // h1 = KAN(y1) pooled directly into g_pool (fused global_add_pool)
    k_scatter<<<scat_blocks, 256>>>(p_h, p_y2, ei);
    k_kan64<<<kan_blocks, TPB, KAN_SMEM>>>(p_y2, (float*)nullptr, (float*)nullptr, p_W1, batch);

    // head
    k_head<<<NGRAPHS, DFEAT>>>(out);
}